// round 14
// baseline (speedup 1.0000x reference)
#include <cuda_runtime.h>

#define SEQ   1024
#define HID   512
#define GATES 2048
#define EMB   512
#define G_CTAS 64       // scan CTAs
#define UNITS_PER 8     // HID / G_CTAS == warps per scan CTA
#define SCAN_THREADS 256
#define NREP 64         // one private replica per CTA (keeps per-line watchers
                        // at 128 lanes despite 8x more polling warps)
#define NBUF 8          // tagged ring depth (power of 2)

// ---------------- device scratch (static, no allocation) ----------------
__device__ float g_xg[SEQ * GATES];              // 8 MB precomputed input gates
// Tagged h stream: 64-bit word = {tag:32 | value:32}. Word for unit u of h_t
// lives at slot t&(NBUF-1), replica r, tag = t+1. Zeroed = h_{-1} with tag 0.
// Zero-init at module load; re-zeroed by xgates_gemm every call.
__device__ unsigned long long g_hp[NBUF][NREP][HID];   // 2 MB

__device__ __forceinline__ float fsigm(float x) {
    return 1.0f / (1.0f + __expf(-x));
}
__device__ __forceinline__ float ftanh(float x) {
    return 2.0f / (1.0f + __expf(-2.0f * x)) - 1.0f;
}

__device__ __forceinline__ unsigned long long ldg_strong(
    const unsigned long long* p) {
    unsigned long long v;
    asm volatile("ld.global.relaxed.gpu.b64 %0, [%1];"
                 : "=l"(v) : "l"(p) : "memory");
    return v;
}
__device__ __forceinline__ void stg_strong(unsigned long long* p,
                                           unsigned long long v) {
    asm volatile("st.global.relaxed.gpu.b64 [%0], %1;"
                 :: "l"(p), "l"(v) : "memory");
}

// ---------------- kernel 1: x_gates GEMM + ring re-init ------------------
// All 512 GEMM blocks re-zero the ring for the NEXT scan:
// 512 blocks x 256 threads x 2 u64 = 262144 words = NBUF*NREP*HID.
__global__ void __launch_bounds__(256) xgates_gemm(
    const int*   __restrict__ tok,
    const float* __restrict__ emb,
    const float* __restrict__ w_ih,
    const float* __restrict__ b_ih,
    const float* __restrict__ b_hh)
{
    __shared__ float As[32][68];
    __shared__ float Bs[32][68];
    __shared__ int   stok[64];

    const int tid = threadIdx.x;
    const int bm = blockIdx.y * 64;
    const int bn = blockIdx.x * 64;

    {   // ring re-init (module-load zeroing covers the very first call)
        int bid = blockIdx.y * gridDim.x + blockIdx.x;   // 0..511
        unsigned long long* z = (unsigned long long*)g_hp + bid * 512 + tid * 2;
        z[0] = 0ull; z[1] = 0ull;
    }

    if (tid < 64) stok[tid] = tok[bm + tid];
    __syncthreads();

    float acc[4][4];
    #pragma unroll
    for (int i = 0; i < 4; i++)
        #pragma unroll
        for (int j = 0; j < 4; j++) acc[i][j] = 0.0f;

    const int tr = tid >> 4;
    const int tc = tid & 15;

    for (int k0 = 0; k0 < EMB; k0 += 32) {
        #pragma unroll
        for (int i = 0; i < 2; i++) {
            int idx = tid + 256 * i;
            int row = idx & 63;
            int k4  = idx >> 6;
            float4 av = *reinterpret_cast<const float4*>(
                emb + (size_t)stok[row] * EMB + k0 + k4 * 4);
            As[k4*4+0][row] = av.x; As[k4*4+1][row] = av.y;
            As[k4*4+2][row] = av.z; As[k4*4+3][row] = av.w;
            float4 bv = *reinterpret_cast<const float4*>(
                w_ih + (size_t)(bn + row) * EMB + k0 + k4 * 4);
            Bs[k4*4+0][row] = bv.x; Bs[k4*4+1][row] = bv.y;
            Bs[k4*4+2][row] = bv.z; Bs[k4*4+3][row] = bv.w;
        }
        __syncthreads();

        #pragma unroll
        for (int kk = 0; kk < 32; kk++) {
            float4 a4 = *reinterpret_cast<const float4*>(&As[kk][tr * 4]);
            float4 b4 = *reinterpret_cast<const float4*>(&Bs[kk][tc * 4]);
            float a[4] = {a4.x, a4.y, a4.z, a4.w};
            float b[4] = {b4.x, b4.y, b4.z, b4.w};
            #pragma unroll
            for (int i = 0; i < 4; i++)
                #pragma unroll
                for (int j = 0; j < 4; j++)
                    acc[i][j] = fmaf(a[i], b[j], acc[i][j]);
        }
        __syncthreads();
    }

    const int gcol = bn + tc * 4;
    float4 bias;
    bias.x = b_ih[gcol + 0] + b_hh[gcol + 0];
    bias.y = b_ih[gcol + 1] + b_hh[gcol + 1];
    bias.z = b_ih[gcol + 2] + b_hh[gcol + 2];
    bias.w = b_ih[gcol + 3] + b_hh[gcol + 3];
    #pragma unroll
    for (int i = 0; i < 4; i++) {
        int trow = bm + tr * 4 + i;
        float4 v;
        v.x = acc[i][0] + bias.x;
        v.y = acc[i][1] + bias.y;
        v.z = acc[i][2] + bias.z;
        v.w = acc[i][3] + bias.w;
        *reinterpret_cast<float4*>(g_xg + (size_t)trow * GATES + gcol) = v;
    }
}

// ---------------- kernel 2: persistent LSTM scan (poll-and-accumulate) ---
// 64 CTAs x 256 threads; warp w owns unit u = base + w. NO barrier, NO smem
// staging in the loop: each lane polls its own 16 tagged words (k = lane+32m)
// directly from the CTA's private replica and FMAs each value the moment its
// tag matches — compute overlaps detection, and only the LAST-arriving word
// gates the short tail (4 FMA + butterfly + gates + publish).
// Safety: every spin is on global words published in earlier steps (proven
// primitive). Any warp publishing tag t+1 first consumed tag t from ALL 512
// units, so when slot t&7 is overwritten every warp chip-wide has advanced
// past any read of that slot's old contents (NBUF=8 >> required depth 2).
// Congestion (R12/R13 lesson): NREP=64 gives each CTA a private replica, so
// per-line watcher count stays at 128 lanes; publish = 2 stores per lane.
__global__ void __launch_bounds__(SCAN_THREADS, 1) lstm_scan(
    const float* __restrict__ w_hh,
    const float* __restrict__ attn_w,
    const float* __restrict__ attn_b,
    float*       __restrict__ out)
{
    const int tid  = threadIdx.x;
    const int warp = tid >> 5;
    const int lane = tid & 31;
    const int base = blockIdx.x * UNITS_PER;
    const int unit = base + warp;
    const int rep  = blockIdx.x;                 // private replica per CTA

    // Weight rows for this warp's unit: gate q row = q*512 + unit.
    // Lane l holds k = l + 32m.
    float w0[16], w1[16], w2[16], w3[16];
    {
        const float* s0 = w_hh + (size_t)(0 * HID + unit) * HID + lane;
        const float* s1 = w_hh + (size_t)(1 * HID + unit) * HID + lane;
        const float* s2 = w_hh + (size_t)(2 * HID + unit) * HID + lane;
        const float* s3 = w_hh + (size_t)(3 * HID + unit) * HID + lane;
        #pragma unroll
        for (int m = 0; m < 16; m++) {
            w0[m] = s0[32 * m]; w1[m] = s1[32 * m];
            w2[m] = s2[32 * m]; w3[m] = s3[32 * m];
        }
    }

    __shared__ float sh_f[HID];   // finalize staging only
    __shared__ float red[8];
    float c_state = 0.0f;

    for (int t = 0; t < SEQ; t++) {
        const unsigned tg = (unsigned)t;

        // xg prefetch: warp-uniform addresses -> LDG broadcast.
        const float* xp = g_xg + (size_t)t * GATES + unit;
        float xg0 = __ldg(xp);
        float xg1 = __ldg(xp + 512);
        float xg2 = __ldg(xp + 1024);
        float xg3 = __ldg(xp + 1536);

        // Poll-and-accumulate: 16 words per lane, FMA on arrival.
        const unsigned long long* gp =
            &g_hp[(t + NBUF - 1) & (NBUF - 1)][rep][lane];
        unsigned long long v[16];
        #pragma unroll
        for (int m = 0; m < 16; m++) v[m] = ldg_strong(gp + 32 * m);

        float a0 = 0.f, a1 = 0.f, a2 = 0.f, a3 = 0.f;
        unsigned pend = 0xffffu;
        do {
            #pragma unroll
            for (int m = 0; m < 16; m++) {
                if (pend & (1u << m)) {
                    if ((unsigned)(v[m] >> 32) == tg) {
                        float h = __uint_as_float((unsigned)v[m]);
                        a0 = fmaf(w0[m], h, a0);
                        a1 = fmaf(w1[m], h, a1);
                        a2 = fmaf(w2[m], h, a2);
                        a3 = fmaf(w3[m], h, a3);
                        pend &= ~(1u << m);
                    } else {
                        v[m] = ldg_strong(gp + 32 * m);
                    }
                }
            }
        } while (pend);

        // Butterfly reduce: all lanes get all 4 sums.
        #pragma unroll
        for (int off = 16; off; off >>= 1) {
            a0 += __shfl_xor_sync(0xffffffffu, a0, off);
            a1 += __shfl_xor_sync(0xffffffffu, a1, off);
            a2 += __shfl_xor_sync(0xffffffffu, a2, off);
            a3 += __shfl_xor_sync(0xffffffffu, a3, off);
        }

        // All lanes redundantly compute gates (same inputs, deterministic).
        float gi = fsigm(a0 + xg0);
        float gf = fsigm(a1 + xg1);
        float gg = ftanh(a2 + xg2);
        float go = fsigm(a3 + xg3);
        c_state = gf * c_state + gi * gg;
        float hn = go * ftanh(c_state);

        // Publish all 64 replicas in parallel: 2 stores per lane.
        unsigned long long pk =
            ((unsigned long long)(tg + 1u) << 32) |
            (unsigned long long)__float_as_uint(hn);
        unsigned long long* d =
            &g_hp[t & (NBUF - 1)][lane * 2][unit];
        stg_strong(d, pk);
        stg_strong(d + HID, pk);                 // replica lane*2+1
    }

    // ---- fused finalize: attention head + outputs (all 64 CTAs) ----
    {
        const unsigned tgF = (unsigned)SEQ;      // tag 1024 = h_1023, slot 7
        const unsigned long long* gp =
            &g_hp[(SEQ + NBUF - 1) & (NBUF - 1)][rep][tid * 2];
        unsigned long long p0 = ldg_strong(gp);
        unsigned long long p1 = ldg_strong(gp + 1);
        while ((unsigned)(p0 >> 32) != tgF) p0 = ldg_strong(gp);
        while ((unsigned)(p1 >> 32) != tgF) p1 = ldg_strong(gp + 1);
        sh_f[tid * 2]     = __uint_as_float((unsigned)p0);
        sh_f[tid * 2 + 1] = __uint_as_float((unsigned)p1);
        __syncthreads();

        const int o = blockIdx.x;                // output unit == CTA id
        float s = fmaf(sh_f[tid * 2],     attn_w[o * HID + tid * 2],
                  sh_f[tid * 2 + 1] * attn_w[o * HID + tid * 2 + 1]);
        #pragma unroll
        for (int off = 16; off; off >>= 1)
            s += __shfl_xor_sync(0xffffffffu, s, off);
        if (lane == 0) red[warp] = s;
        __syncthreads();
        if (tid == 0) {
            float tot = 0.f;
            #pragma unroll
            for (int i = 0; i < 8; i++) tot += red[i];
            red[0] = 1.0f / (1.0f + expf(-(tot + attn_b[o])));
        }
        __syncthreads();
        float a = red[0];
        #pragma unroll
        for (int p = tid; p < 1024; p += SCAN_THREADS)
            out[o * 1024 + p] = a;               // x_attention broadcast
        if (o == 0)
            for (int k = tid; k < HID; k += SCAN_THREADS)
                out[65536 + k] = sh_f[k];        // x_instr_rep
    }
}

// ---------------- launch -------------------------------------------------
extern "C" void kernel_launch(void* const* d_in, const int* in_sizes, int n_in,
                              void* d_out, int out_size)
{
    const int*   tok    = (const int*)  d_in[0];
    const float* emb    = (const float*)d_in[1];
    const float* w_ih   = (const float*)d_in[2];
    const float* w_hh   = (const float*)d_in[3];
    const float* b_ih   = (const float*)d_in[4];
    const float* b_hh   = (const float*)d_in[5];
    const float* attn_w = (const float*)d_in[6];
    const float* attn_b = (const float*)d_in[7];
    float* out = (float*)d_out;

    dim3 gg(GATES / 64, SEQ / 64);           // 32 x 16 blocks
    xgates_gemm<<<gg, 256>>>(tok, emb, w_ih, b_ih, b_hh);
    lstm_scan<<<G_CTAS, SCAN_THREADS>>>(w_hh, attn_w, attn_b, out);
}

// round 16
// speedup vs baseline: 5.1880x; 5.1880x over previous
#include <cuda_runtime.h>

#define SEQ   1024
#define HID   512
#define GATES 2048
#define EMB   512
#define G_CTAS 64       // scan CTAs (R10 config — measured best)
#define UNITS_PER 8     // HID / G_CTAS == warps per scan CTA
#define SCAN_THREADS 256
#define NREP 8          // replicas of the tagged h stream
#define NBUF 8          // tagged ring depth (power of 2)

// Fixed-point scale for integer warp reduction. |lane partial| <= 0.71
// (|w|<=1/sqrt(512), |h|<1, 16 terms), so partial*2^22 <= 3e6 and the
// 32-lane sum <= 9.5e7 << 2^31: overflow-free; quantization ~4e-6 abs.
#define RSCALE 4194304.0f          // 2^22
#define RINV   2.384185791015625e-7f  // 2^-22

// ---------------- device scratch (static, no allocation) ----------------
__device__ float g_xg[SEQ * GATES];              // 8 MB precomputed input gates
// Tagged h stream: 64-bit word = {tag:32 | value:32}. Word for unit u of h_t
// lives at slot t&(NBUF-1), tag = t+1. Zeroed state = h_{-1} with tag 0.
// Zero-init at module load; re-zeroed by xgates_gemm every call.
__device__ unsigned long long g_hp[NBUF][NREP][HID];

__device__ __forceinline__ float fsigm(float x) {
    return 1.0f / (1.0f + __expf(-x));
}
__device__ __forceinline__ float ftanh(float x) {
    return 2.0f / (1.0f + __expf(-2.0f * x)) - 1.0f;
}

__device__ __forceinline__ unsigned long long ldg_strong(
    const unsigned long long* p) {
    unsigned long long v;
    asm volatile("ld.global.relaxed.gpu.b64 %0, [%1];"
                 : "=l"(v) : "l"(p) : "memory");
    return v;
}
__device__ __forceinline__ void stg_strong(unsigned long long* p,
                                           unsigned long long v) {
    asm volatile("st.global.relaxed.gpu.b64 [%0], %1;"
                 :: "l"(p), "l"(v) : "memory");
}

// Integer warp reduction (sm_80+): one instruction, result to all lanes.
// Replaces the 5-level SHFL butterfly (~130 cyc) on the recurrence path.
__device__ __forceinline__ int redux_add_s32(int x) {
    int r;
    asm volatile("redux.sync.add.s32 %0, %1, 0xffffffff;"
                 : "=r"(r) : "r"(x));
    return r;
}
__device__ __forceinline__ float warp_sum_fx(float x) {
    int q = __float2int_rn(x * RSCALE);
    return __int2float_rn(redux_add_s32(q)) * RINV;
}

// ---------------- kernel 1: x_gates GEMM + ring re-init ------------------
__global__ void __launch_bounds__(256) xgates_gemm(
    const int*   __restrict__ tok,
    const float* __restrict__ emb,
    const float* __restrict__ w_ih,
    const float* __restrict__ b_ih,
    const float* __restrict__ b_hh)
{
    __shared__ float As[32][68];
    __shared__ float Bs[32][68];
    __shared__ int   stok[64];

    const int tid = threadIdx.x;
    const int bm = blockIdx.y * 64;
    const int bn = blockIdx.x * 64;

    {   // ring re-init for the NEXT scan (module-load zeroing covers call 1)
        int bid = blockIdx.y * gridDim.x + blockIdx.x;
        if (bid < 128)
            ((unsigned long long*)g_hp)[bid * 256 + tid] = 0ull;
    }

    if (tid < 64) stok[tid] = tok[bm + tid];
    __syncthreads();

    float acc[4][4];
    #pragma unroll
    for (int i = 0; i < 4; i++)
        #pragma unroll
        for (int j = 0; j < 4; j++) acc[i][j] = 0.0f;

    const int tr = tid >> 4;
    const int tc = tid & 15;

    for (int k0 = 0; k0 < EMB; k0 += 32) {
        #pragma unroll
        for (int i = 0; i < 2; i++) {
            int idx = tid + 256 * i;
            int row = idx & 63;
            int k4  = idx >> 6;
            float4 av = *reinterpret_cast<const float4*>(
                emb + (size_t)stok[row] * EMB + k0 + k4 * 4);
            As[k4*4+0][row] = av.x; As[k4*4+1][row] = av.y;
            As[k4*4+2][row] = av.z; As[k4*4+3][row] = av.w;
            float4 bv = *reinterpret_cast<const float4*>(
                w_ih + (size_t)(bn + row) * EMB + k0 + k4 * 4);
            Bs[k4*4+0][row] = bv.x; Bs[k4*4+1][row] = bv.y;
            Bs[k4*4+2][row] = bv.z; Bs[k4*4+3][row] = bv.w;
        }
        __syncthreads();

        #pragma unroll
        for (int kk = 0; kk < 32; kk++) {
            float4 a4 = *reinterpret_cast<const float4*>(&As[kk][tr * 4]);
            float4 b4 = *reinterpret_cast<const float4*>(&Bs[kk][tc * 4]);
            float a[4] = {a4.x, a4.y, a4.z, a4.w};
            float b[4] = {b4.x, b4.y, b4.z, b4.w};
            #pragma unroll
            for (int i = 0; i < 4; i++)
                #pragma unroll
                for (int j = 0; j < 4; j++)
                    acc[i][j] = fmaf(a[i], b[j], acc[i][j]);
        }
        __syncthreads();
    }

    const int gcol = bn + tc * 4;
    float4 bias;
    bias.x = b_ih[gcol + 0] + b_hh[gcol + 0];
    bias.y = b_ih[gcol + 1] + b_hh[gcol + 1];
    bias.z = b_ih[gcol + 2] + b_hh[gcol + 2];
    bias.w = b_ih[gcol + 3] + b_hh[gcol + 3];
    #pragma unroll
    for (int i = 0; i < 4; i++) {
        int trow = bm + tr * 4 + i;
        float4 v;
        v.x = acc[i][0] + bias.x;
        v.y = acc[i][1] + bias.y;
        v.z = acc[i][2] + bias.z;
        v.w = acc[i][3] + bias.w;
        *reinterpret_cast<float4*>(g_xg + (size_t)trow * GATES + gcol) = v;
    }
}

// ---------------- kernel 2: persistent LSTM scan + fused attention head --
// EXACT R10 protocol (measured best: fast-path 4-batch poll, smem stage,
// one barrier, register matvec, parallel replica publish) with two
// compute-path changes:
//  1. Reduction: float->fixed (2^22) -> redux.sync.add.s32 -> float.
//     Serial latency ~74 cyc vs ~130 for the 5-level SHFL butterfly.
//     Provably overflow-free (see RSCALE comment); quantization ~4e-6 abs.
//  2. Consume via LDS.128: lane l owns k = 4l + 128m (m=0..3), weights
//     preloaded in the matching layout — 4 vector loads replace 16 scalar.
__global__ void __launch_bounds__(SCAN_THREADS, 1) lstm_scan(
    const float* __restrict__ w_hh,
    const float* __restrict__ attn_w,
    const float* __restrict__ attn_b,
    float*       __restrict__ out)
{
    const int tid  = threadIdx.x;
    const int warp = tid >> 5;
    const int lane = tid & 31;
    const int base = blockIdx.x * UNITS_PER;
    const int unit = base + warp;
    const int rep  = blockIdx.x & (NREP - 1);

    // Weight rows for this warp's unit: gate q row = q*512 + unit.
    // Lane l holds k = 4l + 128m + j (j=0..3, m=0..3) -> LDS.128 consume.
    float w[4][16];
    #pragma unroll
    for (int q = 0; q < 4; q++) {
        const float* src = w_hh + (size_t)(q * HID + unit) * HID + 4 * lane;
        #pragma unroll
        for (int m = 0; m < 4; m++) {
            float4 v = *reinterpret_cast<const float4*>(src + 128 * m);
            w[q][m*4+0] = v.x; w[q][m*4+1] = v.y;
            w[q][m*4+2] = v.z; w[q][m*4+3] = v.w;
        }
    }

    __shared__ float sh_h[2][HID];
    __shared__ float red[8];
    float c_state = 0.0f;

    for (int t = 0; t < SEQ; t++) {
        const unsigned tg = (unsigned)t;
        float* shb = sh_h[t & 1];

        // xg prefetch: warp-uniform addresses -> LDG broadcast; issued
        // before the poll so latency hides behind the spin.
        const float* xp = g_xg + (size_t)t * GATES + unit;
        float xg0 = __ldg(xp);
        float xg1 = __ldg(xp + 512);
        float xg2 = __ldg(xp + 1024);
        float xg3 = __ldg(xp + 1536);

        // Phase A: pipelined poll of 2 tagged words, stage values to smem.
        {
            const unsigned long long* gp =
                &g_hp[(t + NBUF - 1) & (NBUF - 1)][rep][tid * 2];
            bool d0 = false, d1 = false;
            unsigned long long w0, w1;
            do {
                // Batch of 4 independent samples per word (issue-pipelined).
                unsigned long long s00 = ldg_strong(gp);
                unsigned long long s10 = ldg_strong(gp + 1);
                unsigned long long s01 = ldg_strong(gp);
                unsigned long long s11 = ldg_strong(gp + 1);
                unsigned long long s02 = ldg_strong(gp);
                unsigned long long s12 = ldg_strong(gp + 1);
                unsigned long long s03 = ldg_strong(gp);
                unsigned long long s13 = ldg_strong(gp + 1);
                if (!d0) {
                    if      ((unsigned)(s00 >> 32) == tg) { w0 = s00; d0 = true; }
                    else if ((unsigned)(s01 >> 32) == tg) { w0 = s01; d0 = true; }
                    else if ((unsigned)(s02 >> 32) == tg) { w0 = s02; d0 = true; }
                    else if ((unsigned)(s03 >> 32) == tg) { w0 = s03; d0 = true; }
                }
                if (!d1) {
                    if      ((unsigned)(s10 >> 32) == tg) { w1 = s10; d1 = true; }
                    else if ((unsigned)(s11 >> 32) == tg) { w1 = s11; d1 = true; }
                    else if ((unsigned)(s12 >> 32) == tg) { w1 = s12; d1 = true; }
                    else if ((unsigned)(s13 >> 32) == tg) { w1 = s13; d1 = true; }
                }
            } while (!(d0 && d1));
            shb[tid * 2]     = __uint_as_float((unsigned)w0);
            shb[tid * 2 + 1] = __uint_as_float((unsigned)w1);
        }
        __syncthreads();

        // Phase B: vectorized consume (4x LDS.128) + 64 FMAs.
        float a0 = 0.f, a1 = 0.f, a2 = 0.f, a3 = 0.f;
        #pragma unroll
        for (int m = 0; m < 4; m++) {
            float4 h4 = *reinterpret_cast<const float4*>(&shb[4 * lane + 128 * m]);
            float h[4] = {h4.x, h4.y, h4.z, h4.w};
            #pragma unroll
            for (int j = 0; j < 4; j++) {
                a0 = fmaf(w[0][m*4+j], h[j], a0);
                a1 = fmaf(w[1][m*4+j], h[j], a1);
                a2 = fmaf(w[2][m*4+j], h[j], a2);
                a3 = fmaf(w[3][m*4+j], h[j], a3);
            }
        }
        // Single-instruction integer warp reductions (all lanes get sums).
        a0 = warp_sum_fx(a0);
        a1 = warp_sum_fx(a1);
        a2 = warp_sum_fx(a2);
        a3 = warp_sum_fx(a3);

        // All lanes redundantly compute gates (same inputs, deterministic).
        float gi = fsigm(a0 + xg0);
        float gf = fsigm(a1 + xg1);
        float gg = ftanh(a2 + xg2);
        float go = fsigm(a3 + xg3);
        c_state = gf * c_state + gi * gg;
        float hn = go * ftanh(c_state);

        // Publish: lanes 0..NREP-1 store the replicas in parallel.
        unsigned long long pk =
            ((unsigned long long)(tg + 1u) << 32) |
            (unsigned long long)__float_as_uint(hn);
        if (lane < NREP)
            stg_strong(&g_hp[t & (NBUF - 1)][lane][unit], pk);
    }

    // ---- fused finalize: attention head + outputs (all 64 CTAs) ----
    {
        const unsigned tgF = (unsigned)SEQ;          // tag 1024 = h_1023
        float* shf = sh_h[0];                        // free: last read at t=1022
        const unsigned long long* gp =
            &g_hp[(SEQ + NBUF - 1) & (NBUF - 1)][rep][tid * 2];
        unsigned long long p0 = ldg_strong(gp);
        unsigned long long p1 = ldg_strong(gp + 1);
        while ((unsigned)(p0 >> 32) != tgF) p0 = ldg_strong(gp);
        while ((unsigned)(p1 >> 32) != tgF) p1 = ldg_strong(gp + 1);
        shf[tid * 2]     = __uint_as_float((unsigned)p0);
        shf[tid * 2 + 1] = __uint_as_float((unsigned)p1);
        __syncthreads();

        const int o = blockIdx.x;                    // output unit == CTA id
        float s = fmaf(shf[tid * 2],     attn_w[o * HID + tid * 2],
                  shf[tid * 2 + 1] * attn_w[o * HID + tid * 2 + 1]);
        #pragma unroll
        for (int off = 16; off; off >>= 1)
            s += __shfl_xor_sync(0xffffffffu, s, off);
        if (lane == 0) red[warp] = s;
        __syncthreads();
        if (tid == 0) {
            float tot = 0.f;
            #pragma unroll
            for (int i = 0; i < 8; i++) tot += red[i];
            red[0] = 1.0f / (1.0f + expf(-(tot + attn_b[o])));
        }
        __syncthreads();
        float a = red[0];
        #pragma unroll
        for (int p = tid; p < 1024; p += SCAN_THREADS)
            out[o * 1024 + p] = a;                   // x_attention broadcast
        if (o == 0)
            for (int k = tid; k < HID; k += SCAN_THREADS)
                out[65536 + k] = shf[k];             // x_instr_rep
    }
}

// ---------------- launch -------------------------------------------------
extern "C" void kernel_launch(void* const* d_in, const int* in_sizes, int n_in,
                              void* d_out, int out_size)
{
    const int*   tok    = (const int*)  d_in[0];
    const float* emb    = (const float*)d_in[1];
    const float* w_ih   = (const float*)d_in[2];
    const float* w_hh   = (const float*)d_in[3];
    const float* b_ih   = (const float*)d_in[4];
    const float* b_hh   = (const float*)d_in[5];
    const float* attn_w = (const float*)d_in[6];
    const float* attn_b = (const float*)d_in[7];
    float* out = (float*)d_out;

    dim3 gg(GATES / 64, SEQ / 64);           // 32 x 16 blocks
    xgates_gemm<<<gg, 256>>>(tok, emb, w_ih, b_ih, b_hh);
    lstm_scan<<<G_CTAS, SCAN_THREADS>>>(w_hh, attn_w, attn_b, out);
}

// round 17
// speedup vs baseline: 5.4405x; 1.0487x over previous
#include <cuda_runtime.h>

#define SEQ   1024
#define HID   512
#define GATES 2048
#define EMB   512
#define G_CTAS 128      // scan CTAs: 1 warp/SMSP -> FMA drain 128 cyc not 256
#define UNITS_PER 4     // HID / G_CTAS
#define SCAN_THREADS 128
#define NREP 16         // bid&15 -> 8 CTAs per replica (R10's proven watcher density)
#define NBUF 8          // tagged ring depth (power of 2)

// Fixed-point scale for integer warp reduction (R16 WIN). |lane partial| <=
// 0.71, so partial*2^22 <= 3e6 and the 32-lane sum <= 9.5e7 << 2^31:
// overflow-free; quantization ~4e-6 abs on a pre-activation.
#define RSCALE 4194304.0f             // 2^22
#define RINV   2.384185791015625e-7f  // 2^-22

// ---------------- device scratch (static, no allocation) ----------------
__device__ float g_xg[SEQ * GATES];              // 8 MB precomputed input gates
// Tagged h stream: 64-bit word = {tag:32 | value:32}. Word for unit u of h_t
// lives at slot t&(NBUF-1), tag = t+1. Zeroed state = h_{-1} with tag 0.
// Zero-init at module load; re-zeroed by xgates_gemm every call.
__device__ unsigned long long g_hp[NBUF][NREP][HID];   // 512 KB

__device__ __forceinline__ float fsigm(float x) {
    return 1.0f / (1.0f + __expf(-x));
}
__device__ __forceinline__ float ftanh(float x) {
    return 2.0f / (1.0f + __expf(-2.0f * x)) - 1.0f;
}

__device__ __forceinline__ unsigned long long ldg_strong(
    const unsigned long long* p) {
    unsigned long long v;
    asm volatile("ld.global.relaxed.gpu.b64 %0, [%1];"
                 : "=l"(v) : "l"(p) : "memory");
    return v;
}
__device__ __forceinline__ void stg_strong(unsigned long long* p,
                                           unsigned long long v) {
    asm volatile("st.global.relaxed.gpu.b64 [%0], %1;"
                 :: "l"(p), "l"(v) : "memory");
}

__device__ __forceinline__ int redux_add_s32(int x) {
    int r;
    asm volatile("redux.sync.add.s32 %0, %1, 0xffffffff;"
                 : "=r"(r) : "r"(x));
    return r;
}
__device__ __forceinline__ float warp_sum_fx(float x) {
    int q = __float2int_rn(x * RSCALE);
    return __int2float_rn(redux_add_s32(q)) * RINV;
}

// ---------------- kernel 1: x_gates GEMM + ring re-init ------------------
__global__ void __launch_bounds__(256) xgates_gemm(
    const int*   __restrict__ tok,
    const float* __restrict__ emb,
    const float* __restrict__ w_ih,
    const float* __restrict__ b_ih,
    const float* __restrict__ b_hh)
{
    __shared__ float As[32][68];
    __shared__ float Bs[32][68];
    __shared__ int   stok[64];

    const int tid = threadIdx.x;
    const int bm = blockIdx.y * 64;
    const int bn = blockIdx.x * 64;

    {   // ring re-init for the NEXT scan: 256 blocks x 256 threads x 1 u64
        // = 65536 = NBUF*NREP*HID words (module-load zeroing covers call 1).
        int bid = blockIdx.y * gridDim.x + blockIdx.x;
        if (bid < 256)
            ((unsigned long long*)g_hp)[bid * 256 + tid] = 0ull;
    }

    if (tid < 64) stok[tid] = tok[bm + tid];
    __syncthreads();

    float acc[4][4];
    #pragma unroll
    for (int i = 0; i < 4; i++)
        #pragma unroll
        for (int j = 0; j < 4; j++) acc[i][j] = 0.0f;

    const int tr = tid >> 4;
    const int tc = tid & 15;

    for (int k0 = 0; k0 < EMB; k0 += 32) {
        #pragma unroll
        for (int i = 0; i < 2; i++) {
            int idx = tid + 256 * i;
            int row = idx & 63;
            int k4  = idx >> 6;
            float4 av = *reinterpret_cast<const float4*>(
                emb + (size_t)stok[row] * EMB + k0 + k4 * 4);
            As[k4*4+0][row] = av.x; As[k4*4+1][row] = av.y;
            As[k4*4+2][row] = av.z; As[k4*4+3][row] = av.w;
            float4 bv = *reinterpret_cast<const float4*>(
                w_ih + (size_t)(bn + row) * EMB + k0 + k4 * 4);
            Bs[k4*4+0][row] = bv.x; Bs[k4*4+1][row] = bv.y;
            Bs[k4*4+2][row] = bv.z; Bs[k4*4+3][row] = bv.w;
        }
        __syncthreads();

        #pragma unroll
        for (int kk = 0; kk < 32; kk++) {
            float4 a4 = *reinterpret_cast<const float4*>(&As[kk][tr * 4]);
            float4 b4 = *reinterpret_cast<const float4*>(&Bs[kk][tc * 4]);
            float a[4] = {a4.x, a4.y, a4.z, a4.w};
            float b[4] = {b4.x, b4.y, b4.z, b4.w};
            #pragma unroll
            for (int i = 0; i < 4; i++)
                #pragma unroll
                for (int j = 0; j < 4; j++)
                    acc[i][j] = fmaf(a[i], b[j], acc[i][j]);
        }
        __syncthreads();
    }

    const int gcol = bn + tc * 4;
    float4 bias;
    bias.x = b_ih[gcol + 0] + b_hh[gcol + 0];
    bias.y = b_ih[gcol + 1] + b_hh[gcol + 1];
    bias.z = b_ih[gcol + 2] + b_hh[gcol + 2];
    bias.w = b_ih[gcol + 3] + b_hh[gcol + 3];
    #pragma unroll
    for (int i = 0; i < 4; i++) {
        int trow = bm + tr * 4 + i;
        float4 v;
        v.x = acc[i][0] + bias.x;
        v.y = acc[i][1] + bias.y;
        v.z = acc[i][2] + bias.z;
        v.w = acc[i][3] + bias.w;
        *reinterpret_cast<float4*>(g_xg + (size_t)trow * GATES + gcol) = v;
    }
}

// ---------------- kernel 2: persistent LSTM scan + fused attention head --
// 128 CTAs x 128 threads; warp w (0..3) owns unit u = base + w.
// vs R16 (64x256): per-SM FMA drain halves (512 -> 256 FMA-instr/SM/step,
// 1 warp/SMSP) while NREP=16 keeps the per-replica watcher group at 8 CTAs
// — R11 coupled the drain win to doubled watcher density (rep=bid&7 with
// 128 CTAs) and the two cancelled; this decouples them.
// Protocol otherwise identical: fast-path poll of tagged relaxed.gpu words,
// smem stage, ONE barrier, register matvec (LDS.128 consume), redux.s32
// reduction (R16 WIN), parallel replica publish (lanes 0..15, 1 store each).
__global__ void __launch_bounds__(SCAN_THREADS, 1) lstm_scan(
    const float* __restrict__ w_hh,
    const float* __restrict__ attn_w,
    const float* __restrict__ attn_b,
    float*       __restrict__ out)
{
    const int tid  = threadIdx.x;
    const int warp = tid >> 5;
    const int lane = tid & 31;
    const int base = blockIdx.x * UNITS_PER;
    const int unit = base + warp;
    const int rep  = blockIdx.x & (NREP - 1);

    // Weight rows for this warp's unit: gate q row = q*512 + unit.
    // Lane l holds k = 4l + 128m + j (j=0..3, m=0..3) -> LDS.128 consume.
    float w[4][16];
    #pragma unroll
    for (int q = 0; q < 4; q++) {
        const float* src = w_hh + (size_t)(q * HID + unit) * HID + 4 * lane;
        #pragma unroll
        for (int m = 0; m < 4; m++) {
            float4 v = *reinterpret_cast<const float4*>(src + 128 * m);
            w[q][m*4+0] = v.x; w[q][m*4+1] = v.y;
            w[q][m*4+2] = v.z; w[q][m*4+3] = v.w;
        }
    }

    __shared__ float sh_h[2][HID];
    __shared__ float red[4];
    float c_state = 0.0f;

    for (int t = 0; t < SEQ; t++) {
        const unsigned tg = (unsigned)t;
        float* shb = sh_h[t & 1];

        // xg prefetch: warp-uniform addresses -> LDG broadcast; issued
        // before the poll so latency hides behind the spin.
        const float* xp = g_xg + (size_t)t * GATES + unit;
        float xg0 = __ldg(xp);
        float xg1 = __ldg(xp + 512);
        float xg2 = __ldg(xp + 1024);
        float xg3 = __ldg(xp + 1536);

        // Phase A: poll 4 tagged words (one 32B sector), stage on match.
        {
            const unsigned long long* gp =
                &g_hp[(t + NBUF - 1) & (NBUF - 1)][rep][tid * 4];
            unsigned done = 0u;
            do {
                unsigned long long s0 = ldg_strong(gp);
                unsigned long long s1 = ldg_strong(gp + 1);
                unsigned long long s2 = ldg_strong(gp + 2);
                unsigned long long s3 = ldg_strong(gp + 3);
                if (!(done & 1u) && (unsigned)(s0 >> 32) == tg) {
                    shb[tid * 4 + 0] = __uint_as_float((unsigned)s0); done |= 1u;
                }
                if (!(done & 2u) && (unsigned)(s1 >> 32) == tg) {
                    shb[tid * 4 + 1] = __uint_as_float((unsigned)s1); done |= 2u;
                }
                if (!(done & 4u) && (unsigned)(s2 >> 32) == tg) {
                    shb[tid * 4 + 2] = __uint_as_float((unsigned)s2); done |= 4u;
                }
                if (!(done & 8u) && (unsigned)(s3 >> 32) == tg) {
                    shb[tid * 4 + 3] = __uint_as_float((unsigned)s3); done |= 8u;
                }
            } while (done != 15u);
        }
        __syncthreads();

        // Phase B: vectorized consume (4x LDS.128) + 64 FMAs.
        float a0 = 0.f, a1 = 0.f, a2 = 0.f, a3 = 0.f;
        #pragma unroll
        for (int m = 0; m < 4; m++) {
            float4 h4 = *reinterpret_cast<const float4*>(&shb[4 * lane + 128 * m]);
            float h[4] = {h4.x, h4.y, h4.z, h4.w};
            #pragma unroll
            for (int j = 0; j < 4; j++) {
                a0 = fmaf(w[0][m*4+j], h[j], a0);
                a1 = fmaf(w[1][m*4+j], h[j], a1);
                a2 = fmaf(w[2][m*4+j], h[j], a2);
                a3 = fmaf(w[3][m*4+j], h[j], a3);
            }
        }
        // Single-instruction integer warp reductions (all lanes get sums).
        a0 = warp_sum_fx(a0);
        a1 = warp_sum_fx(a1);
        a2 = warp_sum_fx(a2);
        a3 = warp_sum_fx(a3);

        // All lanes redundantly compute gates (same inputs, deterministic).
        float gi = fsigm(a0 + xg0);
        float gf = fsigm(a1 + xg1);
        float gg = ftanh(a2 + xg2);
        float go = fsigm(a3 + xg3);
        c_state = gf * c_state + gi * gg;
        float hn = go * ftanh(c_state);

        // Publish: lanes 0..NREP-1 store the 16 replicas in parallel.
        unsigned long long pk =
            ((unsigned long long)(tg + 1u) << 32) |
            (unsigned long long)__float_as_uint(hn);
        if (lane < NREP)
            stg_strong(&g_hp[t & (NBUF - 1)][lane][unit], pk);
    }

    // ---- fused finalize: attention head + outputs (CTAs 0..63) ----
    const int o = blockIdx.x;
    if (o < 64) {
        const unsigned tgF = (unsigned)SEQ;          // tag 1024 = h_1023
        float* shf = sh_h[0];                        // free: last read at t=1022
        const unsigned long long* gp =
            &g_hp[(SEQ + NBUF - 1) & (NBUF - 1)][rep][tid * 4];
        #pragma unroll
        for (int i = 0; i < 4; i++) {
            unsigned long long p = ldg_strong(gp + i);
            while ((unsigned)(p >> 32) != tgF) p = ldg_strong(gp + i);
            shf[tid * 4 + i] = __uint_as_float((unsigned)p);
        }
        __syncthreads();

        const float* aw = attn_w + o * HID + tid * 4;
        float s = shf[tid * 4 + 0] * aw[0]
                + shf[tid * 4 + 1] * aw[1]
                + shf[tid * 4 + 2] * aw[2]
                + shf[tid * 4 + 3] * aw[3];
        #pragma unroll
        for (int off = 16; off; off >>= 1)
            s += __shfl_xor_sync(0xffffffffu, s, off);
        if (lane == 0) red[warp] = s;
        __syncthreads();
        if (tid == 0) {
            float tot = red[0] + red[1] + red[2] + red[3];
            red[0] = 1.0f / (1.0f + expf(-(tot + attn_b[o])));
        }
        __syncthreads();
        float a = red[0];
        #pragma unroll
        for (int p = tid; p < 1024; p += SCAN_THREADS)
            out[o * 1024 + p] = a;                   // x_attention broadcast
        if (o == 0)
            for (int k = tid; k < HID; k += SCAN_THREADS)
                out[65536 + k] = shf[k];             // x_instr_rep
    }
}

// ---------------- launch -------------------------------------------------
extern "C" void kernel_launch(void* const* d_in, const int* in_sizes, int n_in,
                              void* d_out, int out_size)
{
    const int*   tok    = (const int*)  d_in[0];
    const float* emb    = (const float*)d_in[1];
    const float* w_ih   = (const float*)d_in[2];
    const float* w_hh   = (const float*)d_in[3];
    const float* b_ih   = (const float*)d_in[4];
    const float* b_hh   = (const float*)d_in[5];
    const float* attn_w = (const float*)d_in[6];
    const float* attn_b = (const float*)d_in[7];
    float* out = (float*)d_out;

    dim3 gg(GATES / 64, SEQ / 64);           // 32 x 16 blocks
    xgates_gemm<<<gg, 256>>>(tok, emb, w_ih, b_ih, b_hh);
    lstm_scan<<<G_CTAS, SCAN_THREADS>>>(w_hh, attn_w, attn_b, out);
}